// round 2
// baseline (speedup 1.0000x reference)
#include <cuda_runtime.h>
#include <math.h>

#define NN 50000
#define NE 800000
#define NG 500
#define CC 64
#define FE 16
#define NL 13          // 1 + 12 PDN convs
#define LSTRIDE 292    // per-layer smem stride for edge MLP weights (16B aligned)

// ---------------- scratch (device globals; no allocation) ----------------
__device__ float  g_h  [NN*CC];
__device__ float  g_cur[NN*CC];
__device__ float  g_acc[NN*CC];
__device__ float  g_ew [NL*NE];     // ew (CSR order) -> overwritten with norm
__device__ float  g_dis[NL*NN];     // deg -> dis (rsqrt) in place
__device__ int    g_cnt[NN];
__device__ int    g_rowptr[NN+1];
__device__ int    g_cursor[NN];
__device__ int    g_eid [NE];
__device__ int    g_csrc[NE];
__device__ int    g_cdst[NE];
__device__ int    g_bsum[256];
__device__ double g_colsum[CC];
__device__ double g_colsq [CC];
__device__ float  g_mu[CC];
__device__ float  g_scale[CC];
__device__ float  g_pool[NG*CC];

// ---------------- init ----------------
__global__ void k_reset() {
    int i = blockIdx.x*blockDim.x + threadIdx.x;
    if (i < NL*NN) g_dis[i] = 1.0f;          // deg starts at self-loop weight 1
    if (i < NN)    g_cnt[i] = 0;
    if (i < NG*CC) g_pool[i] = 0.0f;
}

// ---------------- CSR build ----------------
__global__ void k_hist(const int* __restrict__ dst) {
    int e = blockIdx.x*blockDim.x + threadIdx.x;
    if (e < NE) atomicAdd(&g_cnt[dst[e]], 1);
}

__global__ void k_scan1() {   // per-block sums of counts
    __shared__ int s[256];
    int i = blockIdx.x*256 + threadIdx.x;
    s[threadIdx.x] = (i < NN) ? g_cnt[i] : 0;
    __syncthreads();
    for (int off = 128; off > 0; off >>= 1) {
        if (threadIdx.x < off) s[threadIdx.x] += s[threadIdx.x + off];
        __syncthreads();
    }
    if (threadIdx.x == 0) g_bsum[blockIdx.x] = s[0];
}

__global__ void k_scan2() {   // serial scan over 196 block sums
    if (threadIdx.x == 0) {
        int run = 0;
        for (int b = 0; b < 196; b++) { int t = g_bsum[b]; g_bsum[b] = run; run += t; }
        g_rowptr[NN] = run;
    }
}

__global__ void k_scan3() {   // block-local exclusive scan -> rowptr + cursor
    __shared__ int s[256];
    int t = threadIdx.x;
    int i = blockIdx.x*256 + t;
    int v = (i < NN) ? g_cnt[i] : 0;
    s[t] = v; __syncthreads();
    for (int off = 1; off < 256; off <<= 1) {
        int x = 0; if (t >= off) x = s[t-off];
        __syncthreads();
        s[t] += x;
        __syncthreads();
    }
    if (i < NN) {
        int excl = g_bsum[blockIdx.x] + s[t] - v;
        g_rowptr[i] = excl;
        g_cursor[i] = excl;
    }
}

__global__ void k_scatter(const int* __restrict__ src, const int* __restrict__ dst) {
    int e = blockIdx.x*blockDim.x + threadIdx.x;
    if (e >= NE) return;
    int d = dst[e];
    int p = atomicAdd(&g_cursor[d], 1);
    g_eid[p]  = e;
    g_csrc[p] = src[e];
    g_cdst[p] = d;
}

// ---------------- edge MLPs: all 13 layers in one pass ----------------
__global__ __launch_bounds__(256) void k_edgemlp(
    const float* __restrict__ ea,
    const float* __restrict__ m1W, const float* __restrict__ m1b,
    const float* __restrict__ m2W, const float* __restrict__ m2b,
    const float* __restrict__ hm1W, const float* __restrict__ hm1b,
    const float* __restrict__ hm2W, const float* __restrict__ hm2b)
{
    __shared__ __align__(16) float sw[NL*LSTRIDE];
    // layout per layer l at sw+l*LSTRIDE:
    //   [0..255]   W1 transposed: W1T[j*16+i] = W1[i][j]
    //   [256..271] b1, [272..287] W2, [288] b2
    for (int idx = threadIdx.x; idx < NL*LSTRIDE; idx += 256) {
        int l = idx / LSTRIDE, r = idx - l*LSTRIDE;
        float v = 0.0f;
        if (r < 256) {
            int j = r >> 4, i = r & 15;
            v = (l == 0) ? m1W[i*16 + j] : hm1W[(l-1)*256 + i*16 + j];
        } else if (r < 272) {
            v = (l == 0) ? m1b[r-256] : hm1b[(l-1)*16 + (r-256)];
        } else if (r < 288) {
            v = (l == 0) ? m2W[r-272] : hm2W[(l-1)*16 + (r-272)];
        } else if (r == 288) {
            v = (l == 0) ? m2b[0] : hm2b[l-1];
        }
        sw[idx] = v;
    }
    __syncthreads();

    int p = blockIdx.x*256 + threadIdx.x;
    if (p >= NE) return;
    int e = g_eid[p];
    int d = g_cdst[p];

    float a[16];
    const float4* ap = (const float4*)(ea + e*16);
    #pragma unroll
    for (int q = 0; q < 4; q++) {
        float4 v = ap[q];
        a[4*q+0]=v.x; a[4*q+1]=v.y; a[4*q+2]=v.z; a[4*q+3]=v.w;
    }

    for (int l = 0; l < NL; l++) {
        const float* W = &sw[l*LSTRIDE];
        float z = W[288];
        #pragma unroll
        for (int j = 0; j < 16; j++) {
            const float4* wc = (const float4*)&W[j*16];
            float4 w0 = wc[0], w1 = wc[1], w2 = wc[2], w3 = wc[3];
            float t = W[256+j];
            t=fmaf(a[0],w0.x,t); t=fmaf(a[1],w0.y,t); t=fmaf(a[2],w0.z,t); t=fmaf(a[3],w0.w,t);
            t=fmaf(a[4],w1.x,t); t=fmaf(a[5],w1.y,t); t=fmaf(a[6],w1.z,t); t=fmaf(a[7],w1.w,t);
            t=fmaf(a[8],w2.x,t); t=fmaf(a[9],w2.y,t); t=fmaf(a[10],w2.z,t); t=fmaf(a[11],w2.w,t);
            t=fmaf(a[12],w3.x,t); t=fmaf(a[13],w3.y,t); t=fmaf(a[14],w3.z,t); t=fmaf(a[15],w3.w,t);
            t = fmaxf(t, 0.0f);
            z = fmaf(t, W[272+j], z);
        }
        float ew = 1.0f / (1.0f + __expf(-z));
        g_ew[l*NE + p] = ew;
        atomicAdd(&g_dis[l*NN + d], ew);
    }
}

__global__ void k_rsqrt() {
    int i = blockIdx.x*blockDim.x + threadIdx.x;
    if (i < NL*NN) g_dis[i] = rsqrtf(g_dis[i]);   // deg >= 1 always
}

__global__ void k_norm() {
    int p = blockIdx.x*blockDim.x + threadIdx.x;
    if (p >= NE) return;
    int s = g_csrc[p], d = g_cdst[p];
    #pragma unroll
    for (int l = 0; l < NL; l++)
        g_ew[l*NE + p] *= g_dis[l*NN + s] * g_dis[l*NN + d];
}

// ---------------- fused BN+ReLU+GEMM  (H = act(A) @ W, W is [64][64] k-major) ----------------
#define GSTEP(AV, KIDX) {                                             \
    const float4* wr = (const float4*)&sW[(KIDX)*64];                 \
    _Pragma("unroll")                                                 \
    for (int j = 0; j < 16; j++) {                                    \
        float4 w = wr[j];                                             \
        acc[4*j+0] = fmaf((AV), w.x, acc[4*j+0]);                     \
        acc[4*j+1] = fmaf((AV), w.y, acc[4*j+1]);                     \
        acc[4*j+2] = fmaf((AV), w.z, acc[4*j+2]);                     \
        acc[4*j+3] = fmaf((AV), w.w, acc[4*j+3]);                     \
    } }

__global__ __launch_bounds__(128) void k_gemm(
    const float* __restrict__ A, const float* __restrict__ W,
    float* __restrict__ H, int useBN)
{
    __shared__ __align__(16) float sW[64*64];
    __shared__ float smu[64], ssc[64];
    int t = threadIdx.x;
    const float4* W4 = (const float4*)W;
    float4* sW4 = (float4*)sW;
    #pragma unroll
    for (int i = 0; i < 8; i++) sW4[t + i*128] = W4[t + i*128];
    if (t < 64) { smu[t] = g_mu[t]; ssc[t] = g_scale[t]; }
    __syncthreads();

    int r = blockIdx.x*128 + t;
    if (r >= NN) return;
    const float4* A4 = (const float4*)(A + r*64);
    float acc[64];
    #pragma unroll
    for (int j = 0; j < 64; j++) acc[j] = 0.0f;

    #pragma unroll 4
    for (int g = 0; g < 16; g++) {
        float4 av = A4[g];
        if (useBN) {
            av.x = fmaxf((av.x - smu[4*g+0]) * ssc[4*g+0], 0.0f);
            av.y = fmaxf((av.y - smu[4*g+1]) * ssc[4*g+1], 0.0f);
            av.z = fmaxf((av.z - smu[4*g+2]) * ssc[4*g+2], 0.0f);
            av.w = fmaxf((av.w - smu[4*g+3]) * ssc[4*g+3], 0.0f);
        }
        GSTEP(av.x, 4*g+0);
        GSTEP(av.y, 4*g+1);
        GSTEP(av.z, 4*g+2);
        GSTEP(av.w, 4*g+3);
    }
    float4* H4 = (float4*)(H + r*64);
    #pragma unroll
    for (int j = 0; j < 16; j++) {
        float4 o; o.x=acc[4*j]; o.y=acc[4*j+1]; o.z=acc[4*j+2]; o.w=acc[4*j+3];
        H4[j] = o;
    }
}

// ---------------- BN statistics ----------------
__global__ void k_bnzero() {
    int t = threadIdx.x;
    if (t < CC) { g_colsum[t] = 0.0; g_colsq[t] = 0.0; }
}

__global__ void k_bnstats(const float* __restrict__ A) {
    int t = threadIdx.x;
    int c = t & 63, rg = t >> 6;              // 256 threads: 4 row lanes x 64 cols
    double s = 0.0, q = 0.0;
    for (int r = blockIdx.x*4 + rg; r < NN; r += gridDim.x*4) {
        float v = A[r*64 + c];
        s += v; q += (double)v * v;
    }
    __shared__ double ss[256], sq[256];
    ss[t] = s; sq[t] = q; __syncthreads();
    if (t < 64) {
        double S = ss[t] + ss[t+64] + ss[t+128] + ss[t+192];
        double Q = sq[t] + sq[t+64] + sq[t+128] + sq[t+192];
        atomicAdd(&g_colsum[c], S);
        atomicAdd(&g_colsq[c], Q);
    }
}

__global__ void k_bnfinal() {
    int t = threadIdx.x;
    if (t < CC) {
        double mu  = g_colsum[t] / NN;
        double var = g_colsq[t] / NN - mu*mu;
        if (var < 0.0) var = 0.0;
        g_mu[t]    = (float)mu;
        g_scale[t] = (float)(1.0 / sqrt(var + 1e-5));
    }
}

// ---------------- CSR aggregation: out[d] = sum norm*h[src] + dis^2*h[d] + bias ----------------
__global__ __launch_bounds__(256) void k_agg(
    const float* __restrict__ h, const float* __restrict__ nrm,
    const float* __restrict__ dis, const float* __restrict__ bias,
    float* __restrict__ out)
{
    int w = (blockIdx.x*256 + threadIdx.x) >> 5;
    int lane = threadIdx.x & 31;
    if (w >= NN) return;
    int c = lane*2;
    float dv = dis[w];
    float selfw = dv*dv;
    float2 hv = *(const float2*)(h + w*64 + c);
    float ax = fmaf(selfw, hv.x, bias[c]);
    float ay = fmaf(selfw, hv.y, bias[c+1]);
    int p0 = g_rowptr[w], p1 = g_rowptr[w+1];
    for (int p = p0; p < p1; p++) {
        int s = g_csrc[p];
        float wt = nrm[p];
        float2 v = *(const float2*)(h + s*64 + c);
        ax = fmaf(wt, v.x, ax);
        ay = fmaf(wt, v.y, ay);
    }
    float2 o; o.x = ax; o.y = ay;
    *(float2*)(out + w*64 + c) = o;
}

// ---------------- elementwise helpers ----------------
__global__ void k_copy_acc() {   // acc = cur
    int i = blockIdx.x*blockDim.x + threadIdx.x;
    if (i < NN*CC) g_acc[i] = g_cur[i];
}

__global__ void k_skip() {       // cur += acc; acc += cur(new)
    int i = blockIdx.x*blockDim.x + threadIdx.x;
    if (i < NN*CC) {
        float c = g_cur[i] + g_acc[i];
        g_cur[i] = c;
        g_acc[i] += c;
    }
}

__global__ void k_pool(const int* __restrict__ batch) {
    int i = blockIdx.x*blockDim.x + threadIdx.x;
    if (i >= NN*CC) return;
    int n = i >> 6, c = i & 63;
    float v = fmaxf(g_cur[i], 0.0f);           // relu; >= 0 so int-bit max is valid
    atomicMax((int*)&g_pool[batch[n]*64 + c], __float_as_int(v));
}

__global__ void k_final(const float* __restrict__ linW, const float* __restrict__ linb,
                        float* __restrict__ out) {
    int g = blockIdx.x*blockDim.x + threadIdx.x;
    if (g >= NG) return;
    float a0 = linb[0], a1 = linb[1];
    #pragma unroll 8
    for (int c = 0; c < CC; c++) {
        float v = g_pool[g*64 + c];
        a0 = fmaf(v, linW[c*2+0], a0);
        a1 = fmaf(v, linW[c*2+1], a1);
    }
    out[g*2+0] = a0;
    out[g*2+1] = a1;
}

// ---------------- launch ----------------
extern "C" void kernel_launch(void* const* d_in, const int* in_sizes, int n_in,
                              void* d_out, int out_size)
{
    const float* x     = (const float*)d_in[0];
    const int*   ei    = (const int*)  d_in[1];
    const int*   batch = (const int*)  d_in[2];
    /* d_in[3] = dropout (unused, eval mode) */
    const float* ea    = (const float*)d_in[4];
    const float* Wlin1 = (const float*)d_in[5];
    const float* bias1 = (const float*)d_in[6];
    const float* m1W1  = (const float*)d_in[7];
    const float* m1b1  = (const float*)d_in[8];
    const float* m2W1  = (const float*)d_in[9];
    const float* m2b1  = (const float*)d_in[10];
    const float* hWlin = (const float*)d_in[11];
    const float* hbias = (const float*)d_in[12];
    const float* hm1W  = (const float*)d_in[13];
    const float* hm1b  = (const float*)d_in[14];
    const float* hm2W  = (const float*)d_in[15];
    const float* hm2b  = (const float*)d_in[16];
    const float* linW  = (const float*)d_in[17];
    const float* linb  = (const float*)d_in[18];
    float* out = (float*)d_out;

    const int* src = ei;
    const int* dst = ei + NE;

    float *p_h, *p_cur, *p_ew, *p_dis;
    cudaGetSymbolAddress((void**)&p_h,   g_h);
    cudaGetSymbolAddress((void**)&p_cur, g_cur);
    cudaGetSymbolAddress((void**)&p_ew,  g_ew);
    cudaGetSymbolAddress((void**)&p_dis, g_dis);

    const int EB = (NE + 255) / 256;          // 3125
    const int SB = (NN + 255) / 256;          // 196
    const int XB = (NN*CC + 255) / 256;       // 12500
    const int GB = (NN + 127) / 128;          // 391
    const int AB = (NN*32 + 255) / 256;       // 6250

    // prologue: CSR + all edge norms
    k_reset  <<<(NL*NN + 255)/256, 256>>>();
    k_hist   <<<EB, 256>>>(dst);
    k_scan1  <<<SB, 256>>>();
    k_scan2  <<<1, 32>>>();
    k_scan3  <<<SB, 256>>>();
    k_scatter<<<EB, 256>>>(src, dst);
    k_edgemlp<<<EB, 256>>>(ea, m1W1, m1b1, m2W1, m2b1, hm1W, hm1b, hm2W, hm2b);
    k_rsqrt  <<<(NL*NN + 255)/256, 256>>>();
    k_norm   <<<EB, 256>>>();

    // conv1
    k_gemm<<<GB, 128>>>(x, Wlin1, p_h, 0);
    k_agg <<<AB, 256>>>(p_h, p_ew, p_dis, bias1, p_cur);
    k_copy_acc<<<XB, 256>>>();

    // 12 hidden convs (6 blocks x 2)
    for (int j = 0; j < 12; j++) {
        int l = j + 1;
        k_bnzero <<<1, 64>>>();
        k_bnstats<<<256, 256>>>(p_cur);
        k_bnfinal<<<1, 64>>>();
        k_gemm<<<GB, 128>>>(p_cur, hWlin + j*CC*CC, p_h, 1);
        k_agg <<<AB, 256>>>(p_h, p_ew + l*NE, p_dis + l*NN, hbias + j*CC, p_cur);
        if (j & 1) k_skip<<<XB, 256>>>();
    }

    // relu -> global max pool -> linear readout
    k_pool <<<XB, 256>>>(batch);
    k_final<<<(NG + 63)/64, 64>>>(linW, linb, out);
}